// round 11
// baseline (speedup 1.0000x reference)
#include <cuda_runtime.h>
#include <math.h>
#include <stdint.h>

#define PP  20000
#define MMR 20000
#define NN  16
#define DD  128
#define HH  8
#define DFF 512

#define PL  ((size_t)20000 * 128)   // plane stride for q/k/v (rows * DD)

// ---------------- scratch (static device memory; no allocations) ----------------
// q/k/v stored plane-major: [3][rows][128] for 1-wavefront coalesced gathers.
__device__ float g_q  [(size_t)3 * PL];
__device__ float g_k  [(size_t)3 * PL];
__device__ float g_v  [(size_t)3 * PL];
__device__ float g_t2 [(size_t)PP * DD * 3];
__device__ float g_t2o[(size_t)PP * DD * 3];
__device__ float g_y  [(size_t)PP * DD * 3];
__device__ float g_h1 [(size_t)PP * DFF * 3];
__device__ float g_ff [(size_t)PP * DD * 3];

// duplicated-pair weight images: element (k,o) stored as float2(w,w)
__device__ float2 g_WdD[4][16384];   // Wq, Wk, Wv, Wo  [k*128 + o]
__device__ float2 g_Wd1[2][65536];   // W1, D1          [k*512 + f]
__device__ float2 g_Wd2[65536];      // W2              [k*128 + o]

// Packed fp32x2 FMA (Blackwell): d = a*b + d per 32-bit lane, rn rounding.
__device__ __forceinline__ void fma2(float2& d, const float2 a, const float2 b)
{
    asm("fma.rn.f32x2 %0, %1, %2, %0;"
        : "+l"(*reinterpret_cast<unsigned long long*>(&d))
        : "l"(*reinterpret_cast<const unsigned long long*>(&a)),
          "l"(*reinterpret_cast<const unsigned long long*>(&b)));
}

__device__ __forceinline__ uint32_t smem_u32(const void* p)
{
    return (uint32_t)__cvta_generic_to_shared(p);
}
__device__ __forceinline__ void cp4(uint32_t dst, const void* src)
{
    asm volatile("cp.async.ca.shared.global [%0], [%1], 4;"
                 :: "r"(dst), "l"(src) : "memory");
}
__device__ __forceinline__ void cp16(uint32_t dst, const void* src)
{
    asm volatile("cp.async.cg.shared.global [%0], [%1], 16;"
                 :: "r"(dst), "l"(src) : "memory");
}
#define CP_COMMIT() asm volatile("cp.async.commit_group;" ::: "memory")
#define CP_WAIT1()  asm volatile("cp.async.wait_group 1;" ::: "memory")
#define CP_WAIT0()  asm volatile("cp.async.wait_group 0;" ::: "memory")

// ---------------------------------------------------------------------------
// One-shot weight duplication into (w,w) float2 images. 262144 elements.
// ---------------------------------------------------------------------------
__global__ void dup_weights(const float* __restrict__ Wq, const float* __restrict__ Wk,
                            const float* __restrict__ Wv, const float* __restrict__ Wo,
                            const float* __restrict__ W1, const float* __restrict__ D1,
                            const float* __restrict__ W2)
{
    int e = blockIdx.x * 256 + threadIdx.x;
    if (e < 65536) {
        int w = e >> 14, i = e & 16383;
        const float* src = (w == 0) ? Wq : (w == 1) ? Wk : (w == 2) ? Wv : Wo;
        float v = src[i];
        g_WdD[w][i] = make_float2(v, v);
    } else if (e < 196608) {
        int t = e - 65536;
        int w = t >> 16, i = t & 65535;
        const float* src = w ? D1 : W1;
        float v = src[i];
        g_Wd1[w][i] = make_float2(v, v);
    } else if (e < 262144) {
        int i = e - 196608;
        float v = W2[i];
        g_Wd2[i] = make_float2(v, v);
    }
}

// ---------------------------------------------------------------------------
// VN GEMM, Cout = 128 (round-8 structure, the 974.9us winner).
// CTA: 96 flat rows (32 points) x 128 outs; 128 threads; thread tile 12x8.
// PLANE=1: output in plane-major layout Y[i*PL + pt*128 + o] (for q/k/v).
// ---------------------------------------------------------------------------
template <int K, int PLANE>
__global__ void __launch_bounds__(128, 3)
vn_gemm_db(const float* __restrict__ X, const float2* __restrict__ Wdup,
           float* __restrict__ Y)
{
    const int tid = threadIdx.x;
    const int tx  = tid & 15;
    const int ty  = tid >> 4;
    const int pb  = blockIdx.x * 32;

    __shared__ float  Xs[2][16 * 98];   // 6272 B each
    __shared__ float4 Wd[2][16 * 64];   // 16384 B each

    const uint32_t xs_u = smem_u32(&Xs[0][0]);
    const uint32_t wd_u = smem_u32(&Wd[0][0]);

    float2 acc[6][8] = {};

    auto load_tile = [&](int c0, int buf) {
        const uint32_t xb = xs_u + buf * 6272;
        #pragma unroll
        for (int jj = 0; jj < 12; jj++) {
            int e   = tid + 128 * jj;
            int pt  = e / 48;
            int off = e - pt * 48;
            cp4(xb + (uint32_t)(((off / 3) * 98 + pt * 3 + (off % 3)) * 4),
                X + (size_t)(pb + pt) * (K * 3) + c0 * 3 + off);
        }
        const uint32_t wb = wd_u + buf * 16384;
        const char* wsrc = (const char*)Wdup + (size_t)c0 * 1024;  // 16KB contiguous
        #pragma unroll
        for (int j = 0; j < 8; j++) {
            int u = tid + 128 * j;
            cp16(wb + (uint32_t)(u * 16), wsrc + (size_t)u * 16);
        }
        CP_COMMIT();
    };

    constexpr int NTL = K / 16;
    load_tile(0, 0);

    #pragma unroll 1
    for (int t = 0; t < NTL; t++) {
        const int buf = t & 1;
        if (t + 1 < NTL) {
            load_tile((t + 1) * 16, buf ^ 1);
            CP_WAIT1();
        } else {
            CP_WAIT0();
        }
        __syncthreads();
        #pragma unroll 4
        for (int k = 0; k < 16; k++) {
            float2 A[6];
            #pragma unroll
            for (int m = 0; m < 6; m++)
                A[m] = *reinterpret_cast<const float2*>(&Xs[buf][k * 98 + ty * 12 + 2 * m]);
            #pragma unroll
            for (int j = 0; j < 4; j++) {
                float4 w4 = Wd[buf][k * 64 + tx + 16 * j];
                float2 W0 = make_float2(w4.x, w4.y);
                float2 W1 = make_float2(w4.z, w4.w);
                #pragma unroll
                for (int m = 0; m < 6; m++) {
                    fma2(acc[m][2 * j],     A[m], W0);
                    fma2(acc[m][2 * j + 1], A[m], W1);
                }
            }
        }
        __syncthreads();
    }

    #pragma unroll
    for (int r = 0; r < 12; r++) {
        int pt = pb + 4 * ty + r / 3;
        int i  = r % 3;
        #pragma unroll
        for (int co = 0; co < 8; co++) {
            int o = 2 * (tx + 16 * (co >> 1)) + (co & 1);
            float v = (r & 1) ? acc[r >> 1][co].y : acc[r >> 1][co].x;
            if (PLANE)
                Y[(size_t)i * PL + (size_t)pt * 128 + o] = v;
            else
                Y[(size_t)pt * 384 + o * 3 + i] = v;
        }
    }
}

// ---------------------------------------------------------------------------
// FF1: h1 = vn_relu(Y @ W1, Y @ D1). (round-8 structure, verbatim)
// ---------------------------------------------------------------------------
__global__ void __launch_bounds__(128, 3)
vn_ff1_db(const float* __restrict__ Yin, float* __restrict__ H1)
{
    const int tid = threadIdx.x;
    const int tx  = tid & 15;
    const int ty  = tid >> 4;
    const int pb  = blockIdx.y * 32;
    const int f0  = blockIdx.x * 64;

    __shared__ float  Xs[2][16 * 98];       // 6272 B each
    __shared__ float4 Wd[2][2][16 * 32];    // 8192 B per matrix per buf

    const uint32_t xs_u = smem_u32(&Xs[0][0]);
    const uint32_t wd_u = smem_u32(&Wd[0][0][0]);

    float2 accA[6][4] = {};
    float2 accB[6][4] = {};

    auto load_tile = [&](int c0, int buf) {
        const uint32_t xb = xs_u + buf * 6272;
        #pragma unroll
        for (int jj = 0; jj < 12; jj++) {
            int e   = tid + 128 * jj;
            int pt  = e / 48;
            int off = e - pt * 48;
            cp4(xb + (uint32_t)(((off / 3) * 98 + pt * 3 + (off % 3)) * 4),
                Yin + (size_t)(pb + pt) * (DD * 3) + c0 * 3 + off);
        }
        const uint32_t wb = wd_u + buf * 16384;
        #pragma unroll
        for (int mat = 0; mat < 2; mat++) {
            const char* wsrc = (const char*)&g_Wd1[mat][0];
            #pragma unroll
            for (int j = 0; j < 4; j++) {
                int u  = tid + 128 * j;       // 512 16B units
                int k  = u >> 5;
                int oq = u & 31;
                cp16(wb + (uint32_t)(mat * 8192 + u * 16),
                     wsrc + (size_t)(c0 + k) * 4096 + (size_t)f0 * 8 + (size_t)oq * 16);
            }
        }
        CP_COMMIT();
    };

    constexpr int NTL = DD / 16;
    load_tile(0, 0);

    #pragma unroll 1
    for (int t = 0; t < NTL; t++) {
        const int buf = t & 1;
        if (t + 1 < NTL) {
            load_tile((t + 1) * 16, buf ^ 1);
            CP_WAIT1();
        } else {
            CP_WAIT0();
        }
        __syncthreads();
        #pragma unroll 4
        for (int k = 0; k < 16; k++) {
            float2 A[6];
            #pragma unroll
            for (int m = 0; m < 6; m++)
                A[m] = *reinterpret_cast<const float2*>(&Xs[buf][k * 98 + ty * 12 + 2 * m]);
            #pragma unroll
            for (int j = 0; j < 2; j++) {
                float4 wa4 = Wd[buf][0][k * 32 + tx + 16 * j];
                float4 wb4 = Wd[buf][1][k * 32 + tx + 16 * j];
                float2 Wa0 = make_float2(wa4.x, wa4.y);
                float2 Wa1 = make_float2(wa4.z, wa4.w);
                float2 Wb0 = make_float2(wb4.x, wb4.y);
                float2 Wb1 = make_float2(wb4.z, wb4.w);
                #pragma unroll
                for (int m = 0; m < 6; m++) {
                    fma2(accA[m][2 * j],     A[m], Wa0);
                    fma2(accA[m][2 * j + 1], A[m], Wa1);
                    fma2(accB[m][2 * j],     A[m], Wb0);
                    fma2(accB[m][2 * j + 1], A[m], Wb1);
                }
            }
        }
        __syncthreads();
    }

    #pragma unroll
    for (int ptl = 0; ptl < 4; ptl++) {
        int p = pb + 4 * ty + ptl;
        #pragma unroll
        for (int co = 0; co < 4; co++) {
            int o = f0 + 2 * (tx + 16 * (co >> 1)) + (co & 1);
            float a[3], b[3];
            #pragma unroll
            for (int i = 0; i < 3; i++) {
                int r = 3 * ptl + i;
                a[i] = (r & 1) ? accA[r >> 1][co].y : accA[r >> 1][co].x;
                b[i] = (r & 1) ? accB[r >> 1][co].y : accB[r >> 1][co].x;
            }
            float dot = a[0] * b[0] + a[1] * b[1] + a[2] * b[2];
            float ksq = b[0] * b[0] + b[1] * b[1] + b[2] * b[2];
            float s = (dot >= 0.0f) ? 0.0f : (dot / (ksq + 1e-6f));
            float* hp = H1 + (size_t)p * (DFF * 3) + (size_t)o * 3;
            hp[0] = a[0] - s * b[0];
            hp[1] = a[1] - s * b[1];
            hp[2] = a[2] - s * b[2];
        }
    }
}

// ---------------------------------------------------------------------------
// Attention: one CTA (128 threads) per point p. Thread = channel d.
// q/k/v plane-major: every gather is one fully-coalesced 128B LDG per warp.
// ---------------------------------------------------------------------------
__global__ void attn_kernel(const float* __restrict__ sh,
                            const float* __restrict__ dist,
                            const float* __restrict__ gw1,
                            const float* __restrict__ gb1,
                            const float* __restrict__ gw2,
                            const float* __restrict__ gb2,
                            const int* __restrict__ idxp)
{
    const int p = blockIdx.x;
    const int d = threadIdx.x;
    const int h = d >> 4;

    __shared__ float pos_s[NN][DD];
    __shared__ float sh_s[NN][3];
    __shared__ float att_s[NN][HH];
    __shared__ float rh_s[NN][HH];
    __shared__ int   idx_s[NN];
    __shared__ float w1_s[DD][HH];

    const float* k0p = g_k;
    const float* k1p = g_k + PL;
    const float* k2p = g_k + 2 * PL;
    const float* v0p = g_v;
    const float* v1p = g_v + PL;
    const float* v2p = g_v + 2 * PL;

    size_t qb = (size_t)p * 128 + d;
    float q0 = g_q[qb], q1 = g_q[PL + qb], q2 = g_q[2 * PL + qb];

    if (d < NN) idx_s[d] = idxp[(size_t)p * NN + d];
    if (d < NN * 3) ((float*)sh_s)[d] = sh[(size_t)p * ((NN + 1) * 3) + 3 + d];
    #pragma unroll
    for (int e = d; e < DD * HH; e += 128) ((float*)w1_s)[e] = gw1[e];
    __syncthreads();

    #pragma unroll 4
    for (int n = 0; n < NN; n++) {
        size_t base = (size_t)idx_s[n] * 128 + d;
        float k0 = k0p[base], k1 = k1p[base], k2 = k2p[base];
        float dot = q0 * k0 + q1 * k1 + q2 * k2;
        dot += __shfl_xor_sync(0xffffffffu, dot, 8);
        dot += __shfl_xor_sync(0xffffffffu, dot, 4);
        dot += __shfl_xor_sync(0xffffffffu, dot, 2);
        dot += __shfl_xor_sync(0xffffffffu, dot, 1);
        if ((d & 15) == 0) att_s[n][h] = dot;
        pos_s[n][d] = (k0 - q0) * sh_s[n][0] + (k1 - q1) * sh_s[n][1]
                    + (k2 - q2) * sh_s[n][2];
    }
    __syncthreads();

    {
        int n = d >> 3, j = d & 7;
        float acc = gb1[j];
        const float4* pv = reinterpret_cast<const float4*>(&pos_s[n][0]);
        #pragma unroll 8
        for (int c4 = 0; c4 < DD / 4; c4++) {
            float4 pp = pv[c4];
            acc += pp.x * w1_s[c4 * 4 + 0][j] + pp.y * w1_s[c4 * 4 + 1][j]
                 + pp.z * w1_s[c4 * 4 + 2][j] + pp.w * w1_s[c4 * 4 + 3][j];
        }
        rh_s[n][j] = fmaxf(acc, 0.0f);
    }
    __syncthreads();

    {
        int n = d >> 3, hh = d & 7;
        float acc = gb2[hh];
        #pragma unroll
        for (int j = 0; j < HH; j++) acc += rh_s[n][j] * gw2[j * HH + hh];
        float da = dist[(size_t)p * (NN * HH) + n * HH + hh];
        att_s[n][hh] = (att_s[n][hh] + acc + da) * 0.25f;
    }
    __syncthreads();

    if (d < HH) {
        float m = -1e30f;
        #pragma unroll
        for (int n = 0; n < NN; n++) m = fmaxf(m, att_s[n][d]);
        float s = 0.f;
        #pragma unroll
        for (int n = 0; n < NN; n++) { float e = expf(att_s[n][d] - m); att_s[n][d] = e; s += e; }
        float inv = 1.f / s;
        #pragma unroll
        for (int n = 0; n < NN; n++) att_s[n][d] *= inv;
    }
    __syncthreads();

    float o0 = 0.f, o1 = 0.f, o2 = 0.f;
    #pragma unroll 4
    for (int n = 0; n < NN; n++) {
        float a = att_s[n][h];
        size_t base = (size_t)idx_s[n] * 128 + d;
        o0 += a * v0p[base];
        o1 += a * v1p[base];
        o2 += a * v2p[base];
    }
    float* op = g_t2 + (size_t)p * (DD * 3) + d * 3;
    op[0] = o0; op[1] = o1; op[2] = o2;
}

// ---------------------------------------------------------------------------
// Fused residual + vn_layernorm: O = vn_ln(A + B). grid P, block 128. (round-2)
// ---------------------------------------------------------------------------
__global__ void vn_ln_kernel(const float* __restrict__ A,
                             const float* __restrict__ B,
                             const float* __restrict__ gam,
                             const float* __restrict__ bet,
                             float* __restrict__ O)
{
    const int p = blockIdx.x;
    const int d = threadIdx.x;
    size_t base = (size_t)p * (DD * 3) + d * 3;
    float z0 = A[base + 0] + B[base + 0];
    float z1 = A[base + 1] + B[base + 1];
    float z2 = A[base + 2] + B[base + 2];
    float n = sqrtf(z0 * z0 + z1 * z1 + z2 * z2);

    float s1 = n, s2 = n * n;
    #pragma unroll
    for (int off = 16; off; off >>= 1) {
        s1 += __shfl_xor_sync(0xffffffffu, s1, off);
        s2 += __shfl_xor_sync(0xffffffffu, s2, off);
    }
    __shared__ float sm1[4], sm2[4];
    int w = d >> 5;
    if ((d & 31) == 0) { sm1[w] = s1; sm2[w] = s2; }
    __syncthreads();
    float S1 = sm1[0] + sm1[1] + sm1[2] + sm1[3];
    float S2 = sm2[0] + sm2[1] + sm2[2] + sm2[3];
    float mu  = S1 * (1.0f / DD);
    float var = S2 * (1.0f / DD) - mu * mu;
    float nh  = (n - mu) * rsqrtf(var + 1e-5f) * gam[d] + bet[d];
    float sc  = nh / (n + 1e-6f);
    O[base + 0] = z0 * sc;
    O[base + 1] = z1 * sc;
    O[base + 2] = z2 * sc;
}

// ---------------------------------------------------------------------------
extern "C" void kernel_launch(void* const* d_in, const int* in_sizes, int n_in,
                              void* d_out, int out_size)
{
    const float* tgt   = (const float*)d_in[0];
    const float* mem   = (const float*)d_in[1];
    const float* sh    = (const float*)d_in[2];
    const float* dist  = (const float*)d_in[3];
    const float* Wq    = (const float*)d_in[4];
    const float* Wk    = (const float*)d_in[5];
    const float* Wv    = (const float*)d_in[6];
    const float* Wo    = (const float*)d_in[7];
    const float* gw1   = (const float*)d_in[8];
    const float* gb1   = (const float*)d_in[9];
    const float* gw2   = (const float*)d_in[10];
    const float* gb2   = (const float*)d_in[11];
    const float* ln1g  = (const float*)d_in[12];
    const float* ln1b  = (const float*)d_in[13];
    const float* ln2g  = (const float*)d_in[14];
    const float* ln2b  = (const float*)d_in[15];
    const float* ffw1  = (const float*)d_in[16];
    const float* ffd1  = (const float*)d_in[17];
    const float* ffw2  = (const float*)d_in[18];
    const int*   idxp  = (const int*)d_in[19];
    float* out = (float*)d_out;

    float *q, *k, *v, *t2, *t2o, *y, *h1, *ff;
    cudaGetSymbolAddress((void**)&q,   g_q);
    cudaGetSymbolAddress((void**)&k,   g_k);
    cudaGetSymbolAddress((void**)&v,   g_v);
    cudaGetSymbolAddress((void**)&t2,  g_t2);
    cudaGetSymbolAddress((void**)&t2o, g_t2o);
    cudaGetSymbolAddress((void**)&y,   g_y);
    cudaGetSymbolAddress((void**)&h1,  g_h1);
    cudaGetSymbolAddress((void**)&ff,  g_ff);
    float2 *wdD, *wd2;
    cudaGetSymbolAddress((void**)&wdD, g_WdD);
    cudaGetSymbolAddress((void**)&wd2, g_Wd2);

    const int NT = PP / 32;   // 625 point tiles

    dup_weights<<<1024, 256>>>(Wq, Wk, Wv, Wo, ffw1, ffd1, ffw2);

    vn_gemm_db<DD, 1><<<NT, 128>>>(tgt, wdD + 0 * 16384, q);
    vn_gemm_db<DD, 1><<<NT, 128>>>(mem, wdD + 1 * 16384, k);
    vn_gemm_db<DD, 1><<<NT, 128>>>(mem, wdD + 2 * 16384, v);

    attn_kernel<<<PP, 128>>>(sh, dist, gw1, gb1, gw2, gb2, idxp);

    vn_gemm_db<DD, 0><<<NT, 128>>>(t2, wdD + 3 * 16384, t2o);
    vn_ln_kernel<<<PP, 128>>>(tgt, t2o, ln1g, ln1b, y);

    vn_ff1_db<<<dim3(DFF / 64, NT), 128>>>(y, h1);
    vn_gemm_db<DFF, 0><<<NT, 128>>>(h1, wd2, ff);
    vn_ln_kernel<<<PP, 128>>>(y, ff, ln2g, ln2b, out);
}

// round 12
// speedup vs baseline: 1.0860x; 1.0860x over previous
#include <cuda_runtime.h>
#include <math.h>
#include <stdint.h>

#define PP  20000
#define MMR 20000
#define NN  16
#define DD  128
#define HH  8
#define DFF 512

#define PL  ((size_t)20000 * 128)   // plane stride for q/k/v (rows * DD)

// ---------------- scratch (static device memory; no allocations) ----------------
// q/k/v stored plane-major: [3][rows][128] for 1-wavefront coalesced gathers.
__device__ float g_q  [(size_t)3 * PL];
__device__ float g_k  [(size_t)3 * PL];
__device__ float g_v  [(size_t)3 * PL];
__device__ float g_t2 [(size_t)PP * DD * 3];
__device__ float g_t2o[(size_t)PP * DD * 3];
__device__ float g_y  [(size_t)PP * DD * 3];
__device__ float g_h1 [(size_t)PP * DFF * 3];
__device__ float g_ff [(size_t)PP * DD * 3];

// duplicated-pair weight images: element (k,o) stored as float2(w,w)
__device__ float2 g_WdD[4][16384];   // Wq, Wk, Wv, Wo  [k*128 + o]
__device__ float2 g_Wd1[2][65536];   // W1, D1          [k*512 + f]
__device__ float2 g_Wd2[65536];      // W2              [k*128 + o]

// Packed fp32x2 FMA (Blackwell): d = a*b + d per 32-bit lane, rn rounding.
__device__ __forceinline__ void fma2(float2& d, const float2 a, const float2 b)
{
    asm("fma.rn.f32x2 %0, %1, %2, %0;"
        : "+l"(*reinterpret_cast<unsigned long long*>(&d))
        : "l"(*reinterpret_cast<const unsigned long long*>(&a)),
          "l"(*reinterpret_cast<const unsigned long long*>(&b)));
}

__device__ __forceinline__ uint32_t smem_u32(const void* p)
{
    return (uint32_t)__cvta_generic_to_shared(p);
}
__device__ __forceinline__ void cp4(uint32_t dst, const void* src)
{
    asm volatile("cp.async.ca.shared.global [%0], [%1], 4;"
                 :: "r"(dst), "l"(src) : "memory");
}
__device__ __forceinline__ void cp16(uint32_t dst, const void* src)
{
    asm volatile("cp.async.cg.shared.global [%0], [%1], 16;"
                 :: "r"(dst), "l"(src) : "memory");
}
#define CP_COMMIT() asm volatile("cp.async.commit_group;" ::: "memory")
#define CP_WAIT1()  asm volatile("cp.async.wait_group 1;" ::: "memory")
#define CP_WAIT0()  asm volatile("cp.async.wait_group 0;" ::: "memory")

// ---------------------------------------------------------------------------
// One-shot weight duplication into (w,w) float2 images. 262144 elements.
// ---------------------------------------------------------------------------
__global__ void dup_weights(const float* __restrict__ Wq, const float* __restrict__ Wk,
                            const float* __restrict__ Wv, const float* __restrict__ Wo,
                            const float* __restrict__ W1, const float* __restrict__ D1,
                            const float* __restrict__ W2)
{
    int e = blockIdx.x * 256 + threadIdx.x;
    if (e < 65536) {
        int w = e >> 14, i = e & 16383;
        const float* src = (w == 0) ? Wq : (w == 1) ? Wk : (w == 2) ? Wv : Wo;
        float v = src[i];
        g_WdD[w][i] = make_float2(v, v);
    } else if (e < 196608) {
        int t = e - 65536;
        int w = t >> 16, i = t & 65535;
        const float* src = w ? D1 : W1;
        float v = src[i];
        g_Wd1[w][i] = make_float2(v, v);
    } else if (e < 262144) {
        int i = e - 196608;
        float v = W2[i];
        g_Wd2[i] = make_float2(v, v);
    }
}

// ---------------------------------------------------------------------------
// Merged q/k/v GEMM: grid 1875 = 625 point-tiles x 3 (which = bid % 3).
// which 0: q = tgt @ Wq; 1: k = mem @ Wk; 2: v = mem @ Wv. Plane outputs.
// Round-8 12x8 tile, cp.async double buffer. 84% wave efficiency vs 70%.
// ---------------------------------------------------------------------------
__global__ void __launch_bounds__(128, 3)
qkv_gemm(const float* __restrict__ Xq, const float* __restrict__ Xkv,
         float* __restrict__ Yq, float* __restrict__ Yk, float* __restrict__ Yv)
{
    const int tid = threadIdx.x;
    const int tx  = tid & 15;
    const int ty  = tid >> 4;
    const int which = blockIdx.x % 3;
    const int pb  = (blockIdx.x / 3) * 32;

    const float*  X = (which == 0) ? Xq : Xkv;
    const float2* Wdup = &g_WdD[which][0];
    float* Y = (which == 0) ? Yq : (which == 1) ? Yk : Yv;

    __shared__ float  Xs[2][16 * 98];   // 6272 B each
    __shared__ float4 Wd[2][16 * 64];   // 16384 B each

    const uint32_t xs_u = smem_u32(&Xs[0][0]);
    const uint32_t wd_u = smem_u32(&Wd[0][0]);

    float2 acc[6][8] = {};

    auto load_tile = [&](int c0, int buf) {
        const uint32_t xb = xs_u + buf * 6272;
        #pragma unroll
        for (int jj = 0; jj < 12; jj++) {
            int e   = tid + 128 * jj;
            int pt  = e / 48;
            int off = e - pt * 48;
            cp4(xb + (uint32_t)(((off / 3) * 98 + pt * 3 + (off % 3)) * 4),
                X + (size_t)(pb + pt) * (DD * 3) + c0 * 3 + off);
        }
        const uint32_t wb = wd_u + buf * 16384;
        const char* wsrc = (const char*)Wdup + (size_t)c0 * 1024;
        #pragma unroll
        for (int j = 0; j < 8; j++) {
            int u = tid + 128 * j;
            cp16(wb + (uint32_t)(u * 16), wsrc + (size_t)u * 16);
        }
        CP_COMMIT();
    };

    constexpr int NTL = DD / 16;
    load_tile(0, 0);

    #pragma unroll 1
    for (int t = 0; t < NTL; t++) {
        const int buf = t & 1;
        if (t + 1 < NTL) {
            load_tile((t + 1) * 16, buf ^ 1);
            CP_WAIT1();
        } else {
            CP_WAIT0();
        }
        __syncthreads();
        #pragma unroll 4
        for (int k = 0; k < 16; k++) {
            float2 A[6];
            #pragma unroll
            for (int m = 0; m < 6; m++)
                A[m] = *reinterpret_cast<const float2*>(&Xs[buf][k * 98 + ty * 12 + 2 * m]);
            #pragma unroll
            for (int j = 0; j < 4; j++) {
                float4 w4 = Wd[buf][k * 64 + tx + 16 * j];
                float2 W0 = make_float2(w4.x, w4.y);
                float2 W1 = make_float2(w4.z, w4.w);
                #pragma unroll
                for (int m = 0; m < 6; m++) {
                    fma2(acc[m][2 * j],     A[m], W0);
                    fma2(acc[m][2 * j + 1], A[m], W1);
                }
            }
        }
        __syncthreads();
    }

    #pragma unroll
    for (int r = 0; r < 12; r++) {
        int pt = pb + 4 * ty + r / 3;
        int i  = r % 3;
        #pragma unroll
        for (int co = 0; co < 8; co++) {
            int o = 2 * (tx + 16 * (co >> 1)) + (co & 1);
            float v = (r & 1) ? acc[r >> 1][co].y : acc[r >> 1][co].x;
            Y[(size_t)i * PL + (size_t)pt * 128 + o] = v;
        }
    }
}

// ---------------------------------------------------------------------------
// VN GEMM, Cout = 128, standard interleaved output (Wo). Round-8 verbatim.
// ---------------------------------------------------------------------------
template <int K>
__global__ void __launch_bounds__(128, 3)
vn_gemm_db(const float* __restrict__ X, const float2* __restrict__ Wdup,
           float* __restrict__ Y)
{
    const int tid = threadIdx.x;
    const int tx  = tid & 15;
    const int ty  = tid >> 4;
    const int pb  = blockIdx.x * 32;

    __shared__ float  Xs[2][16 * 98];
    __shared__ float4 Wd[2][16 * 64];

    const uint32_t xs_u = smem_u32(&Xs[0][0]);
    const uint32_t wd_u = smem_u32(&Wd[0][0]);

    float2 acc[6][8] = {};

    auto load_tile = [&](int c0, int buf) {
        const uint32_t xb = xs_u + buf * 6272;
        #pragma unroll
        for (int jj = 0; jj < 12; jj++) {
            int e   = tid + 128 * jj;
            int pt  = e / 48;
            int off = e - pt * 48;
            cp4(xb + (uint32_t)(((off / 3) * 98 + pt * 3 + (off % 3)) * 4),
                X + (size_t)(pb + pt) * (K * 3) + c0 * 3 + off);
        }
        const uint32_t wb = wd_u + buf * 16384;
        const char* wsrc = (const char*)Wdup + (size_t)c0 * 1024;
        #pragma unroll
        for (int j = 0; j < 8; j++) {
            int u = tid + 128 * j;
            cp16(wb + (uint32_t)(u * 16), wsrc + (size_t)u * 16);
        }
        CP_COMMIT();
    };

    constexpr int NTL = K / 16;
    load_tile(0, 0);

    #pragma unroll 1
    for (int t = 0; t < NTL; t++) {
        const int buf = t & 1;
        if (t + 1 < NTL) {
            load_tile((t + 1) * 16, buf ^ 1);
            CP_WAIT1();
        } else {
            CP_WAIT0();
        }
        __syncthreads();
        #pragma unroll 4
        for (int k = 0; k < 16; k++) {
            float2 A[6];
            #pragma unroll
            for (int m = 0; m < 6; m++)
                A[m] = *reinterpret_cast<const float2*>(&Xs[buf][k * 98 + ty * 12 + 2 * m]);
            #pragma unroll
            for (int j = 0; j < 4; j++) {
                float4 w4 = Wd[buf][k * 64 + tx + 16 * j];
                float2 W0 = make_float2(w4.x, w4.y);
                float2 W1 = make_float2(w4.z, w4.w);
                #pragma unroll
                for (int m = 0; m < 6; m++) {
                    fma2(acc[m][2 * j],     A[m], W0);
                    fma2(acc[m][2 * j + 1], A[m], W1);
                }
            }
        }
        __syncthreads();
    }

    #pragma unroll
    for (int r = 0; r < 12; r++) {
        int pt = pb + 4 * ty + r / 3;
        int i  = r % 3;
        #pragma unroll
        for (int co = 0; co < 8; co++) {
            int o = 2 * (tx + 16 * (co >> 1)) + (co & 1);
            float v = (r & 1) ? acc[r >> 1][co].y : acc[r >> 1][co].x;
            Y[(size_t)pt * 384 + o * 3 + i] = v;
        }
    }
}

// ---------------------------------------------------------------------------
// FF2 col-split (round-9 structure): grid 1250, CTA 32 pts x 64 outs,
// thread 12x4, 2-buf cp.async. 94% wave efficiency at occupancy 4.
// ---------------------------------------------------------------------------
template <int K>
__global__ void __launch_bounds__(128, 4)
vn_gemm_cs_db(const float* __restrict__ X, const float2* __restrict__ Wdup,
              float* __restrict__ Y)
{
    const int tid = threadIdx.x;
    const int tx  = tid & 15;
    const int ty  = tid >> 4;
    const int pb  = (blockIdx.x >> 1) * 32;
    const int o0  = (blockIdx.x & 1) * 64;

    __shared__ float  Xs[2][16 * 98];   // 6272 B each
    __shared__ float4 Wd[2][16 * 32];   // 8192 B each

    const uint32_t xs_u = smem_u32(&Xs[0][0]);
    const uint32_t wd_u = smem_u32(&Wd[0][0]);

    float2 acc[6][4] = {};

    auto load_tile = [&](int c0, int buf) {
        const uint32_t xb = xs_u + buf * 6272;
        #pragma unroll
        for (int jj = 0; jj < 12; jj++) {
            int e   = tid + 128 * jj;
            int pt  = e / 48;
            int off = e - pt * 48;
            cp4(xb + (uint32_t)(((off / 3) * 98 + pt * 3 + (off % 3)) * 4),
                X + (size_t)(pb + pt) * (K * 3) + c0 * 3 + off);
        }
        const uint32_t wb = wd_u + buf * 8192;
        const char* wsrc = (const char*)Wdup + (size_t)c0 * 1024 + (size_t)o0 * 8;
        #pragma unroll
        for (int j = 0; j < 4; j++) {
            int u  = tid + 128 * j;      // 512 16B units: k = u>>5, uo = u&31
            int k  = u >> 5;
            int uo = u & 31;
            cp16(wb + (uint32_t)(u * 16), wsrc + (size_t)k * 1024 + (size_t)uo * 16);
        }
        CP_COMMIT();
    };

    constexpr int NTL = K / 16;
    load_tile(0, 0);

    #pragma unroll 1
    for (int t = 0; t < NTL; t++) {
        const int buf = t & 1;
        if (t + 1 < NTL) {
            load_tile((t + 1) * 16, buf ^ 1);
            CP_WAIT1();
        } else {
            CP_WAIT0();
        }
        __syncthreads();
        #pragma unroll 4
        for (int k = 0; k < 16; k++) {
            float2 A[6];
            #pragma unroll
            for (int m = 0; m < 6; m++)
                A[m] = *reinterpret_cast<const float2*>(&Xs[buf][k * 98 + ty * 12 + 2 * m]);
            #pragma unroll
            for (int j = 0; j < 2; j++) {
                float4 w4 = Wd[buf][k * 32 + tx + 16 * j];
                float2 W0 = make_float2(w4.x, w4.y);
                float2 W1 = make_float2(w4.z, w4.w);
                #pragma unroll
                for (int m = 0; m < 6; m++) {
                    fma2(acc[m][2 * j],     A[m], W0);
                    fma2(acc[m][2 * j + 1], A[m], W1);
                }
            }
        }
        __syncthreads();
    }

    #pragma unroll
    for (int r = 0; r < 12; r++) {
        int pt = pb + 4 * ty + r / 3;
        int i  = r % 3;
        #pragma unroll
        for (int co = 0; co < 4; co++) {
            int o = o0 + 2 * (tx + 16 * (co >> 1)) + (co & 1);
            float v = (r & 1) ? acc[r >> 1][co].y : acc[r >> 1][co].x;
            Y[(size_t)pt * 384 + o * 3 + i] = v;
        }
    }
}

// ---------------------------------------------------------------------------
// FF1: h1 = vn_relu(Y @ W1, Y @ D1). (round-8 structure, verbatim)
// ---------------------------------------------------------------------------
__global__ void __launch_bounds__(128, 3)
vn_ff1_db(const float* __restrict__ Yin, float* __restrict__ H1)
{
    const int tid = threadIdx.x;
    const int tx  = tid & 15;
    const int ty  = tid >> 4;
    const int pb  = blockIdx.y * 32;
    const int f0  = blockIdx.x * 64;

    __shared__ float  Xs[2][16 * 98];       // 6272 B each
    __shared__ float4 Wd[2][2][16 * 32];    // 8192 B per matrix per buf

    const uint32_t xs_u = smem_u32(&Xs[0][0]);
    const uint32_t wd_u = smem_u32(&Wd[0][0][0]);

    float2 accA[6][4] = {};
    float2 accB[6][4] = {};

    auto load_tile = [&](int c0, int buf) {
        const uint32_t xb = xs_u + buf * 6272;
        #pragma unroll
        for (int jj = 0; jj < 12; jj++) {
            int e   = tid + 128 * jj;
            int pt  = e / 48;
            int off = e - pt * 48;
            cp4(xb + (uint32_t)(((off / 3) * 98 + pt * 3 + (off % 3)) * 4),
                Yin + (size_t)(pb + pt) * (DD * 3) + c0 * 3 + off);
        }
        const uint32_t wb = wd_u + buf * 16384;
        #pragma unroll
        for (int mat = 0; mat < 2; mat++) {
            const char* wsrc = (const char*)&g_Wd1[mat][0];
            #pragma unroll
            for (int j = 0; j < 4; j++) {
                int u  = tid + 128 * j;       // 512 16B units
                int k  = u >> 5;
                int oq = u & 31;
                cp16(wb + (uint32_t)(mat * 8192 + u * 16),
                     wsrc + (size_t)(c0 + k) * 4096 + (size_t)f0 * 8 + (size_t)oq * 16);
            }
        }
        CP_COMMIT();
    };

    constexpr int NTL = DD / 16;
    load_tile(0, 0);

    #pragma unroll 1
    for (int t = 0; t < NTL; t++) {
        const int buf = t & 1;
        if (t + 1 < NTL) {
            load_tile((t + 1) * 16, buf ^ 1);
            CP_WAIT1();
        } else {
            CP_WAIT0();
        }
        __syncthreads();
        #pragma unroll 4
        for (int k = 0; k < 16; k++) {
            float2 A[6];
            #pragma unroll
            for (int m = 0; m < 6; m++)
                A[m] = *reinterpret_cast<const float2*>(&Xs[buf][k * 98 + ty * 12 + 2 * m]);
            #pragma unroll
            for (int j = 0; j < 2; j++) {
                float4 wa4 = Wd[buf][0][k * 32 + tx + 16 * j];
                float4 wb4 = Wd[buf][1][k * 32 + tx + 16 * j];
                float2 Wa0 = make_float2(wa4.x, wa4.y);
                float2 Wa1 = make_float2(wa4.z, wa4.w);
                float2 Wb0 = make_float2(wb4.x, wb4.y);
                float2 Wb1 = make_float2(wb4.z, wb4.w);
                #pragma unroll
                for (int m = 0; m < 6; m++) {
                    fma2(accA[m][2 * j],     A[m], Wa0);
                    fma2(accA[m][2 * j + 1], A[m], Wa1);
                    fma2(accB[m][2 * j],     A[m], Wb0);
                    fma2(accB[m][2 * j + 1], A[m], Wb1);
                }
            }
        }
        __syncthreads();
    }

    #pragma unroll
    for (int ptl = 0; ptl < 4; ptl++) {
        int p = pb + 4 * ty + ptl;
        #pragma unroll
        for (int co = 0; co < 4; co++) {
            int o = f0 + 2 * (tx + 16 * (co >> 1)) + (co & 1);
            float a[3], b[3];
            #pragma unroll
            for (int i = 0; i < 3; i++) {
                int r = 3 * ptl + i;
                a[i] = (r & 1) ? accA[r >> 1][co].y : accA[r >> 1][co].x;
                b[i] = (r & 1) ? accB[r >> 1][co].y : accB[r >> 1][co].x;
            }
            float dot = a[0] * b[0] + a[1] * b[1] + a[2] * b[2];
            float ksq = b[0] * b[0] + b[1] * b[1] + b[2] * b[2];
            float s = (dot >= 0.0f) ? 0.0f : (dot / (ksq + 1e-6f));
            float* hp = H1 + (size_t)p * (DFF * 3) + (size_t)o * 3;
            hp[0] = a[0] - s * b[0];
            hp[1] = a[1] - s * b[1];
            hp[2] = a[2] - s * b[2];
        }
    }
}

// ---------------------------------------------------------------------------
// Attention: one CTA (128 threads) per point p. Thread = channel d.
// q/k/v plane-major: every gather is one fully-coalesced 128B LDG per warp.
// ---------------------------------------------------------------------------
__global__ void attn_kernel(const float* __restrict__ sh,
                            const float* __restrict__ dist,
                            const float* __restrict__ gw1,
                            const float* __restrict__ gb1,
                            const float* __restrict__ gw2,
                            const float* __restrict__ gb2,
                            const int* __restrict__ idxp)
{
    const int p = blockIdx.x;
    const int d = threadIdx.x;
    const int h = d >> 4;

    __shared__ float pos_s[NN][DD];
    __shared__ float sh_s[NN][3];
    __shared__ float att_s[NN][HH];
    __shared__ float rh_s[NN][HH];
    __shared__ int   idx_s[NN];
    __shared__ float w1_s[DD][HH];

    const float* k0p = g_k;
    const float* k1p = g_k + PL;
    const float* k2p = g_k + 2 * PL;
    const float* v0p = g_v;
    const float* v1p = g_v + PL;
    const float* v2p = g_v + 2 * PL;

    size_t qb = (size_t)p * 128 + d;
    float q0 = g_q[qb], q1 = g_q[PL + qb], q2 = g_q[2 * PL + qb];

    if (d < NN) idx_s[d] = idxp[(size_t)p * NN + d];
    if (d < NN * 3) ((float*)sh_s)[d] = sh[(size_t)p * ((NN + 1) * 3) + 3 + d];
    #pragma unroll
    for (int e = d; e < DD * HH; e += 128) ((float*)w1_s)[e] = gw1[e];
    __syncthreads();

    #pragma unroll 4
    for (int n = 0; n < NN; n++) {
        size_t base = (size_t)idx_s[n] * 128 + d;
        float k0 = k0p[base], k1 = k1p[base], k2 = k2p[base];
        float dot = q0 * k0 + q1 * k1 + q2 * k2;
        dot += __shfl_xor_sync(0xffffffffu, dot, 8);
        dot += __shfl_xor_sync(0xffffffffu, dot, 4);
        dot += __shfl_xor_sync(0xffffffffu, dot, 2);
        dot += __shfl_xor_sync(0xffffffffu, dot, 1);
        if ((d & 15) == 0) att_s[n][h] = dot;
        pos_s[n][d] = (k0 - q0) * sh_s[n][0] + (k1 - q1) * sh_s[n][1]
                    + (k2 - q2) * sh_s[n][2];
    }
    __syncthreads();

    {
        int n = d >> 3, j = d & 7;
        float acc = gb1[j];
        const float4* pv = reinterpret_cast<const float4*>(&pos_s[n][0]);
        #pragma unroll 8
        for (int c4 = 0; c4 < DD / 4; c4++) {
            float4 pp = pv[c4];
            acc += pp.x * w1_s[c4 * 4 + 0][j] + pp.y * w1_s[c4 * 4 + 1][j]
                 + pp.z * w1_s[c4 * 4 + 2][j] + pp.w * w1_s[c4 * 4 + 3][j];
        }
        rh_s[n][j] = fmaxf(acc, 0.0f);
    }
    __syncthreads();

    {
        int n = d >> 3, hh = d & 7;
        float acc = gb2[hh];
        #pragma unroll
        for (int j = 0; j < HH; j++) acc += rh_s[n][j] * gw2[j * HH + hh];
        float da = dist[(size_t)p * (NN * HH) + n * HH + hh];
        att_s[n][hh] = (att_s[n][hh] + acc + da) * 0.25f;
    }
    __syncthreads();

    if (d < HH) {
        float m = -1e30f;
        #pragma unroll
        for (int n = 0; n < NN; n++) m = fmaxf(m, att_s[n][d]);
        float s = 0.f;
        #pragma unroll
        for (int n = 0; n < NN; n++) { float e = expf(att_s[n][d] - m); att_s[n][d] = e; s += e; }
        float inv = 1.f / s;
        #pragma unroll
        for (int n = 0; n < NN; n++) att_s[n][d] *= inv;
    }
    __syncthreads();

    float o0 = 0.f, o1 = 0.f, o2 = 0.f;
    #pragma unroll 4
    for (int n = 0; n < NN; n++) {
        float a = att_s[n][h];
        size_t base = (size_t)idx_s[n] * 128 + d;
        o0 += a * v0p[base];
        o1 += a * v1p[base];
        o2 += a * v2p[base];
    }
    float* op = g_t2 + (size_t)p * (DD * 3) + d * 3;
    op[0] = o0; op[1] = o1; op[2] = o2;
}

// ---------------------------------------------------------------------------
// Fused residual + vn_layernorm: O = vn_ln(A + B). grid P, block 128.
// ---------------------------------------------------------------------------
__global__ void vn_ln_kernel(const float* __restrict__ A,
                             const float* __restrict__ B,
                             const float* __restrict__ gam,
                             const float* __restrict__ bet,
                             float* __restrict__ O)
{
    const int p = blockIdx.x;
    const int d = threadIdx.x;
    size_t base = (size_t)p * (DD * 3) + d * 3;
    float z0 = A[base + 0] + B[base + 0];
    float z1 = A[base + 1] + B[base + 1];
    float z2 = A[base + 2] + B[base + 2];
    float n = sqrtf(z0 * z0 + z1 * z1 + z2 * z2);

    float s1 = n, s2 = n * n;
    #pragma unroll
    for (int off = 16; off; off >>= 1) {
        s1 += __shfl_xor_sync(0xffffffffu, s1, off);
        s2 += __shfl_xor_sync(0xffffffffu, s2, off);
    }
    __shared__ float sm1[4], sm2[4];
    int w = d >> 5;
    if ((d & 31) == 0) { sm1[w] = s1; sm2[w] = s2; }
    __syncthreads();
    float S1 = sm1[0] + sm1[1] + sm1[2] + sm1[3];
    float S2 = sm2[0] + sm2[1] + sm2[2] + sm2[3];
    float mu  = S1 * (1.0f / DD);
    float var = S2 * (1.0f / DD) - mu * mu;
    float nh  = (n - mu) * rsqrtf(var + 1e-5f) * gam[d] + bet[d];
    float sc  = nh / (n + 1e-6f);
    O[base + 0] = z0 * sc;
    O[base + 1] = z1 * sc;
    O[base + 2] = z2 * sc;
}

// ---------------------------------------------------------------------------
extern "C" void kernel_launch(void* const* d_in, const int* in_sizes, int n_in,
                              void* d_out, int out_size)
{
    const float* tgt   = (const float*)d_in[0];
    const float* mem   = (const float*)d_in[1];
    const float* sh    = (const float*)d_in[2];
    const float* dist  = (const float*)d_in[3];
    const float* Wq    = (const float*)d_in[4];
    const float* Wk    = (const float*)d_in[5];
    const float* Wv    = (const float*)d_in[6];
    const float* Wo    = (const float*)d_in[7];
    const float* gw1   = (const float*)d_in[8];
    const float* gb1   = (const float*)d_in[9];
    const float* gw2   = (const float*)d_in[10];
    const float* gb2   = (const float*)d_in[11];
    const float* ln1g  = (const float*)d_in[12];
    const float* ln1b  = (const float*)d_in[13];
    const float* ln2g  = (const float*)d_in[14];
    const float* ln2b  = (const float*)d_in[15];
    const float* ffw1  = (const float*)d_in[16];
    const float* ffd1  = (const float*)d_in[17];
    const float* ffw2  = (const float*)d_in[18];
    const int*   idxp  = (const int*)d_in[19];
    float* out = (float*)d_out;

    float *q, *k, *v, *t2, *t2o, *y, *h1, *ff;
    cudaGetSymbolAddress((void**)&q,   g_q);
    cudaGetSymbolAddress((void**)&k,   g_k);
    cudaGetSymbolAddress((void**)&v,   g_v);
    cudaGetSymbolAddress((void**)&t2,  g_t2);
    cudaGetSymbolAddress((void**)&t2o, g_t2o);
    cudaGetSymbolAddress((void**)&y,   g_y);
    cudaGetSymbolAddress((void**)&h1,  g_h1);
    cudaGetSymbolAddress((void**)&ff,  g_ff);
    float2 *wdD, *wd2;
    cudaGetSymbolAddress((void**)&wdD, g_WdD);
    cudaGetSymbolAddress((void**)&wd2, g_Wd2);

    const int NT = PP / 32;   // 625 point tiles

    dup_weights<<<1024, 256>>>(Wq, Wk, Wv, Wo, ffw1, ffd1, ffw2);

    // merged q/k/v: 1875 CTAs, which = bid % 3 (k/v of same tile adjacent)
    qkv_gemm<<<NT * 3, 128>>>(tgt, mem, q, k, v);

    attn_kernel<<<PP, 128>>>(sh, dist, gw1, gb1, gw2, gb2, idxp);

    vn_gemm_db<DD><<<NT, 128>>>(t2, wdD + 3 * 16384, t2o);
    vn_ln_kernel<<<PP, 128>>>(tgt, t2o, ln1g, ln1b, y);

    vn_ff1_db<<<dim3(DFF / 64, NT), 128>>>(y, h1);
    vn_gemm_cs_db<DFF><<<NT * 2, 128>>>(h1, wd2, ff);
    vn_ln_kernel<<<PP, 128>>>(y, ff, ln2g, ln2b, out);
}

// round 13
// speedup vs baseline: 1.1183x; 1.0297x over previous
#include <cuda_runtime.h>
#include <math.h>
#include <stdint.h>

#define PP  20000
#define MMR 20000
#define NN  16
#define DD  128
#define HH  8
#define DFF 512

#define PL  ((size_t)20000 * 128)   // plane stride (rows * DD)

// ---------------- scratch (static device memory; no allocations) ----------------
// q/k/v, t2o, ff stored plane-major: [3][rows][128].
__device__ float g_q  [(size_t)3 * PL];
__device__ float g_k  [(size_t)3 * PL];
__device__ float g_v  [(size_t)3 * PL];
__device__ float g_t2 [(size_t)PP * DD * 3];
__device__ float g_t2o[(size_t)3 * PL];
__device__ float g_y  [(size_t)PP * DD * 3];
__device__ float g_h1 [(size_t)PP * DFF * 3];
__device__ float g_ff [(size_t)3 * PL];

// duplicated-pair weight images: element (k,o) stored as float2(w,w)
__device__ float2 g_WdD[4][16384];   // Wq, Wk, Wv, Wo  [k*128 + o]
__device__ float2 g_Wd1[2][65536];   // W1, D1          [k*512 + f]
__device__ float2 g_Wd2[65536];      // W2              [k*128 + o]

// Packed fp32x2 FMA (Blackwell): d = a*b + d per 32-bit lane, rn rounding.
__device__ __forceinline__ void fma2(float2& d, const float2 a, const float2 b)
{
    asm("fma.rn.f32x2 %0, %1, %2, %0;"
        : "+l"(*reinterpret_cast<unsigned long long*>(&d))
        : "l"(*reinterpret_cast<const unsigned long long*>(&a)),
          "l"(*reinterpret_cast<const unsigned long long*>(&b)));
}

__device__ __forceinline__ uint32_t smem_u32(const void* p)
{
    return (uint32_t)__cvta_generic_to_shared(p);
}
__device__ __forceinline__ void cp4(uint32_t dst, const void* src)
{
    asm volatile("cp.async.ca.shared.global [%0], [%1], 4;"
                 :: "r"(dst), "l"(src) : "memory");
}
__device__ __forceinline__ void cp16(uint32_t dst, const void* src)
{
    asm volatile("cp.async.cg.shared.global [%0], [%1], 16;"
                 :: "r"(dst), "l"(src) : "memory");
}
#define CP_COMMIT() asm volatile("cp.async.commit_group;" ::: "memory")
#define CP_WAIT1()  asm volatile("cp.async.wait_group 1;" ::: "memory")
#define CP_WAIT0()  asm volatile("cp.async.wait_group 0;" ::: "memory")

// ---------------------------------------------------------------------------
// One-shot weight duplication into (w,w) float2 images. 262144 elements.
// ---------------------------------------------------------------------------
__global__ void dup_weights(const float* __restrict__ Wq, const float* __restrict__ Wk,
                            const float* __restrict__ Wv, const float* __restrict__ Wo,
                            const float* __restrict__ W1, const float* __restrict__ D1,
                            const float* __restrict__ W2)
{
    int e = blockIdx.x * 256 + threadIdx.x;
    if (e < 65536) {
        int w = e >> 14, i = e & 16383;
        const float* src = (w == 0) ? Wq : (w == 1) ? Wk : (w == 2) ? Wv : Wo;
        float v = src[i];
        g_WdD[w][i] = make_float2(v, v);
    } else if (e < 196608) {
        int t = e - 65536;
        int w = t >> 16, i = t & 65535;
        const float* src = w ? D1 : W1;
        float v = src[i];
        g_Wd1[w][i] = make_float2(v, v);
    } else if (e < 262144) {
        int i = e - 196608;
        float v = W2[i];
        g_Wd2[i] = make_float2(v, v);
    }
}

// ---------------------------------------------------------------------------
// Merged q/k/v GEMM: grid 1875 = 625 point-tiles x 3 (which = bid % 3).
// Plane outputs. Round-8 12x8 tile, cp.async double buffer.
// ---------------------------------------------------------------------------
__global__ void __launch_bounds__(128, 3)
qkv_gemm(const float* __restrict__ Xq, const float* __restrict__ Xkv,
         float* __restrict__ Yq, float* __restrict__ Yk, float* __restrict__ Yv)
{
    const int tid = threadIdx.x;
    const int tx  = tid & 15;
    const int ty  = tid >> 4;
    const int which = blockIdx.x % 3;
    const int pb  = (blockIdx.x / 3) * 32;

    const float*  X = (which == 0) ? Xq : Xkv;
    const float2* Wdup = &g_WdD[which][0];
    float* Y = (which == 0) ? Yq : (which == 1) ? Yk : Yv;

    __shared__ float  Xs[2][16 * 98];   // 6272 B each
    __shared__ float4 Wd[2][16 * 64];   // 16384 B each

    const uint32_t xs_u = smem_u32(&Xs[0][0]);
    const uint32_t wd_u = smem_u32(&Wd[0][0]);

    float2 acc[6][8] = {};

    auto load_tile = [&](int c0, int buf) {
        const uint32_t xb = xs_u + buf * 6272;
        #pragma unroll
        for (int jj = 0; jj < 12; jj++) {
            int e   = tid + 128 * jj;
            int pt  = e / 48;
            int off = e - pt * 48;
            cp4(xb + (uint32_t)(((off / 3) * 98 + pt * 3 + (off % 3)) * 4),
                X + (size_t)(pb + pt) * (DD * 3) + c0 * 3 + off);
        }
        const uint32_t wb = wd_u + buf * 16384;
        const char* wsrc = (const char*)Wdup + (size_t)c0 * 1024;
        #pragma unroll
        for (int j = 0; j < 8; j++) {
            int u = tid + 128 * j;
            cp16(wb + (uint32_t)(u * 16), wsrc + (size_t)u * 16);
        }
        CP_COMMIT();
    };

    constexpr int NTL = DD / 16;
    load_tile(0, 0);

    #pragma unroll 1
    for (int t = 0; t < NTL; t++) {
        const int buf = t & 1;
        if (t + 1 < NTL) {
            load_tile((t + 1) * 16, buf ^ 1);
            CP_WAIT1();
        } else {
            CP_WAIT0();
        }
        __syncthreads();
        #pragma unroll 4
        for (int k = 0; k < 16; k++) {
            float2 A[6];
            #pragma unroll
            for (int m = 0; m < 6; m++)
                A[m] = *reinterpret_cast<const float2*>(&Xs[buf][k * 98 + ty * 12 + 2 * m]);
            #pragma unroll
            for (int j = 0; j < 4; j++) {
                float4 w4 = Wd[buf][k * 64 + tx + 16 * j];
                float2 W0 = make_float2(w4.x, w4.y);
                float2 W1 = make_float2(w4.z, w4.w);
                #pragma unroll
                for (int m = 0; m < 6; m++) {
                    fma2(acc[m][2 * j],     A[m], W0);
                    fma2(acc[m][2 * j + 1], A[m], W1);
                }
            }
        }
        __syncthreads();
    }

    #pragma unroll
    for (int r = 0; r < 12; r++) {
        int pt = pb + 4 * ty + r / 3;
        int i  = r % 3;
        #pragma unroll
        for (int co = 0; co < 8; co++) {
            int o = 2 * (tx + 16 * (co >> 1)) + (co & 1);
            float v = (r & 1) ? acc[r >> 1][co].y : acc[r >> 1][co].x;
            Y[(size_t)i * PL + (size_t)pt * 128 + o] = v;
        }
    }
}

// ---------------------------------------------------------------------------
// VN GEMM, Cout = 128, plane-major output (Wo -> t2o planes).
// Round-8 structure; PLANE epilogue measured at 59.2us for this config.
// ---------------------------------------------------------------------------
template <int K>
__global__ void __launch_bounds__(128, 3)
vn_gemm_db_pl(const float* __restrict__ X, const float2* __restrict__ Wdup,
              float* __restrict__ Y)
{
    const int tid = threadIdx.x;
    const int tx  = tid & 15;
    const int ty  = tid >> 4;
    const int pb  = blockIdx.x * 32;

    __shared__ float  Xs[2][16 * 98];
    __shared__ float4 Wd[2][16 * 64];

    const uint32_t xs_u = smem_u32(&Xs[0][0]);
    const uint32_t wd_u = smem_u32(&Wd[0][0]);

    float2 acc[6][8] = {};

    auto load_tile = [&](int c0, int buf) {
        const uint32_t xb = xs_u + buf * 6272;
        #pragma unroll
        for (int jj = 0; jj < 12; jj++) {
            int e   = tid + 128 * jj;
            int pt  = e / 48;
            int off = e - pt * 48;
            cp4(xb + (uint32_t)(((off / 3) * 98 + pt * 3 + (off % 3)) * 4),
                X + (size_t)(pb + pt) * (K * 3) + c0 * 3 + off);
        }
        const uint32_t wb = wd_u + buf * 16384;
        const char* wsrc = (const char*)Wdup + (size_t)c0 * 1024;
        #pragma unroll
        for (int j = 0; j < 8; j++) {
            int u = tid + 128 * j;
            cp16(wb + (uint32_t)(u * 16), wsrc + (size_t)u * 16);
        }
        CP_COMMIT();
    };

    constexpr int NTL = K / 16;
    load_tile(0, 0);

    #pragma unroll 1
    for (int t = 0; t < NTL; t++) {
        const int buf = t & 1;
        if (t + 1 < NTL) {
            load_tile((t + 1) * 16, buf ^ 1);
            CP_WAIT1();
        } else {
            CP_WAIT0();
        }
        __syncthreads();
        #pragma unroll 4
        for (int k = 0; k < 16; k++) {
            float2 A[6];
            #pragma unroll
            for (int m = 0; m < 6; m++)
                A[m] = *reinterpret_cast<const float2*>(&Xs[buf][k * 98 + ty * 12 + 2 * m]);
            #pragma unroll
            for (int j = 0; j < 4; j++) {
                float4 w4 = Wd[buf][k * 64 + tx + 16 * j];
                float2 W0 = make_float2(w4.x, w4.y);
                float2 W1 = make_float2(w4.z, w4.w);
                #pragma unroll
                for (int m = 0; m < 6; m++) {
                    fma2(acc[m][2 * j],     A[m], W0);
                    fma2(acc[m][2 * j + 1], A[m], W1);
                }
            }
        }
        __syncthreads();
    }

    #pragma unroll
    for (int r = 0; r < 12; r++) {
        int pt = pb + 4 * ty + r / 3;
        int i  = r % 3;
        #pragma unroll
        for (int co = 0; co < 8; co++) {
            int o = 2 * (tx + 16 * (co >> 1)) + (co & 1);
            float v = (r & 1) ? acc[r >> 1][co].y : acc[r >> 1][co].x;
            Y[(size_t)i * PL + (size_t)pt * 128 + o] = v;
        }
    }
}

// ---------------------------------------------------------------------------
// FF2 col-split with plane-major output: grid 1250, CTA 32 pts x 64 outs,
// thread 12x4, 2-buf cp.async, occupancy 4.
// ---------------------------------------------------------------------------
template <int K>
__global__ void __launch_bounds__(128, 4)
vn_gemm_cs_db_pl(const float* __restrict__ X, const float2* __restrict__ Wdup,
                 float* __restrict__ Y)
{
    const int tid = threadIdx.x;
    const int tx  = tid & 15;
    const int ty  = tid >> 4;
    const int pb  = (blockIdx.x >> 1) * 32;
    const int o0  = (blockIdx.x & 1) * 64;

    __shared__ float  Xs[2][16 * 98];   // 6272 B each
    __shared__ float4 Wd[2][16 * 32];   // 8192 B each

    const uint32_t xs_u = smem_u32(&Xs[0][0]);
    const uint32_t wd_u = smem_u32(&Wd[0][0]);

    float2 acc[6][4] = {};

    auto load_tile = [&](int c0, int buf) {
        const uint32_t xb = xs_u + buf * 6272;
        #pragma unroll
        for (int jj = 0; jj < 12; jj++) {
            int e   = tid + 128 * jj;
            int pt  = e / 48;
            int off = e - pt * 48;
            cp4(xb + (uint32_t)(((off / 3) * 98 + pt * 3 + (off % 3)) * 4),
                X + (size_t)(pb + pt) * (K * 3) + c0 * 3 + off);
        }
        const uint32_t wb = wd_u + buf * 8192;
        const char* wsrc = (const char*)Wdup + (size_t)c0 * 1024 + (size_t)o0 * 8;
        #pragma unroll
        for (int j = 0; j < 4; j++) {
            int u  = tid + 128 * j;      // 512 16B units: k = u>>5, uo = u&31
            int k  = u >> 5;
            int uo = u & 31;
            cp16(wb + (uint32_t)(u * 16), wsrc + (size_t)k * 1024 + (size_t)uo * 16);
        }
        CP_COMMIT();
    };

    constexpr int NTL = K / 16;
    load_tile(0, 0);

    #pragma unroll 1
    for (int t = 0; t < NTL; t++) {
        const int buf = t & 1;
        if (t + 1 < NTL) {
            load_tile((t + 1) * 16, buf ^ 1);
            CP_WAIT1();
        } else {
            CP_WAIT0();
        }
        __syncthreads();
        #pragma unroll 4
        for (int k = 0; k < 16; k++) {
            float2 A[6];
            #pragma unroll
            for (int m = 0; m < 6; m++)
                A[m] = *reinterpret_cast<const float2*>(&Xs[buf][k * 98 + ty * 12 + 2 * m]);
            #pragma unroll
            for (int j = 0; j < 2; j++) {
                float4 w4 = Wd[buf][k * 32 + tx + 16 * j];
                float2 W0 = make_float2(w4.x, w4.y);
                float2 W1 = make_float2(w4.z, w4.w);
                #pragma unroll
                for (int m = 0; m < 6; m++) {
                    fma2(acc[m][2 * j],     A[m], W0);
                    fma2(acc[m][2 * j + 1], A[m], W1);
                }
            }
        }
        __syncthreads();
    }

    #pragma unroll
    for (int r = 0; r < 12; r++) {
        int pt = pb + 4 * ty + r / 3;
        int i  = r % 3;
        #pragma unroll
        for (int co = 0; co < 4; co++) {
            int o = o0 + 2 * (tx + 16 * (co >> 1)) + (co & 1);
            float v = (r & 1) ? acc[r >> 1][co].y : acc[r >> 1][co].x;
            Y[(size_t)i * PL + (size_t)pt * 128 + o] = v;
        }
    }
}

// ---------------------------------------------------------------------------
// FF1: h1 = vn_relu(Y @ W1, Y @ D1). (round-8 structure, verbatim)
// ---------------------------------------------------------------------------
__global__ void __launch_bounds__(128, 3)
vn_ff1_db(const float* __restrict__ Yin, float* __restrict__ H1)
{
    const int tid = threadIdx.x;
    const int tx  = tid & 15;
    const int ty  = tid >> 4;
    const int pb  = blockIdx.y * 32;
    const int f0  = blockIdx.x * 64;

    __shared__ float  Xs[2][16 * 98];       // 6272 B each
    __shared__ float4 Wd[2][2][16 * 32];    // 8192 B per matrix per buf

    const uint32_t xs_u = smem_u32(&Xs[0][0]);
    const uint32_t wd_u = smem_u32(&Wd[0][0][0]);

    float2 accA[6][4] = {};
    float2 accB[6][4] = {};

    auto load_tile = [&](int c0, int buf) {
        const uint32_t xb = xs_u + buf * 6272;
        #pragma unroll
        for (int jj = 0; jj < 12; jj++) {
            int e   = tid + 128 * jj;
            int pt  = e / 48;
            int off = e - pt * 48;
            cp4(xb + (uint32_t)(((off / 3) * 98 + pt * 3 + (off % 3)) * 4),
                Yin + (size_t)(pb + pt) * (DD * 3) + c0 * 3 + off);
        }
        const uint32_t wb = wd_u + buf * 16384;
        #pragma unroll
        for (int mat = 0; mat < 2; mat++) {
            const char* wsrc = (const char*)&g_Wd1[mat][0];
            #pragma unroll
            for (int j = 0; j < 4; j++) {
                int u  = tid + 128 * j;       // 512 16B units
                int k  = u >> 5;
                int oq = u & 31;
                cp16(wb + (uint32_t)(mat * 8192 + u * 16),
                     wsrc + (size_t)(c0 + k) * 4096 + (size_t)f0 * 8 + (size_t)oq * 16);
            }
        }
        CP_COMMIT();
    };

    constexpr int NTL = DD / 16;
    load_tile(0, 0);

    #pragma unroll 1
    for (int t = 0; t < NTL; t++) {
        const int buf = t & 1;
        if (t + 1 < NTL) {
            load_tile((t + 1) * 16, buf ^ 1);
            CP_WAIT1();
        } else {
            CP_WAIT0();
        }
        __syncthreads();
        #pragma unroll 4
        for (int k = 0; k < 16; k++) {
            float2 A[6];
            #pragma unroll
            for (int m = 0; m < 6; m++)
                A[m] = *reinterpret_cast<const float2*>(&Xs[buf][k * 98 + ty * 12 + 2 * m]);
            #pragma unroll
            for (int j = 0; j < 2; j++) {
                float4 wa4 = Wd[buf][0][k * 32 + tx + 16 * j];
                float4 wb4 = Wd[buf][1][k * 32 + tx + 16 * j];
                float2 Wa0 = make_float2(wa4.x, wa4.y);
                float2 Wa1 = make_float2(wa4.z, wa4.w);
                float2 Wb0 = make_float2(wb4.x, wb4.y);
                float2 Wb1 = make_float2(wb4.z, wb4.w);
                #pragma unroll
                for (int m = 0; m < 6; m++) {
                    fma2(accA[m][2 * j],     A[m], Wa0);
                    fma2(accA[m][2 * j + 1], A[m], Wa1);
                    fma2(accB[m][2 * j],     A[m], Wb0);
                    fma2(accB[m][2 * j + 1], A[m], Wb1);
                }
            }
        }
        __syncthreads();
    }

    #pragma unroll
    for (int ptl = 0; ptl < 4; ptl++) {
        int p = pb + 4 * ty + ptl;
        #pragma unroll
        for (int co = 0; co < 4; co++) {
            int o = f0 + 2 * (tx + 16 * (co >> 1)) + (co & 1);
            float a[3], b[3];
            #pragma unroll
            for (int i = 0; i < 3; i++) {
                int r = 3 * ptl + i;
                a[i] = (r & 1) ? accA[r >> 1][co].y : accA[r >> 1][co].x;
                b[i] = (r & 1) ? accB[r >> 1][co].y : accB[r >> 1][co].x;
            }
            float dot = a[0] * b[0] + a[1] * b[1] + a[2] * b[2];
            float ksq = b[0] * b[0] + b[1] * b[1] + b[2] * b[2];
            float s = (dot >= 0.0f) ? 0.0f : (dot / (ksq + 1e-6f));
            float* hp = H1 + (size_t)p * (DFF * 3) + (size_t)o * 3;
            hp[0] = a[0] - s * b[0];
            hp[1] = a[1] - s * b[1];
            hp[2] = a[2] - s * b[2];
        }
    }
}

// ---------------------------------------------------------------------------
// Attention: one CTA (128 threads) per point p. Thread = channel d.
// q/k/v plane-major: every gather is one fully-coalesced 128B LDG per warp.
// ---------------------------------------------------------------------------
__global__ void attn_kernel(const float* __restrict__ sh,
                            const float* __restrict__ dist,
                            const float* __restrict__ gw1,
                            const float* __restrict__ gb1,
                            const float* __restrict__ gw2,
                            const float* __restrict__ gb2,
                            const int* __restrict__ idxp)
{
    const int p = blockIdx.x;
    const int d = threadIdx.x;
    const int h = d >> 4;

    __shared__ float pos_s[NN][DD];
    __shared__ float sh_s[NN][3];
    __shared__ float att_s[NN][HH];
    __shared__ float rh_s[NN][HH];
    __shared__ int   idx_s[NN];
    __shared__ float w1_s[DD][HH];

    const float* k0p = g_k;
    const float* k1p = g_k + PL;
    const float* k2p = g_k + 2 * PL;
    const float* v0p = g_v;
    const float* v1p = g_v + PL;
    const float* v2p = g_v + 2 * PL;

    size_t qb = (size_t)p * 128 + d;
    float q0 = g_q[qb], q1 = g_q[PL + qb], q2 = g_q[2 * PL + qb];

    if (d < NN) idx_s[d] = idxp[(size_t)p * NN + d];
    if (d < NN * 3) ((float*)sh_s)[d] = sh[(size_t)p * ((NN + 1) * 3) + 3 + d];
    #pragma unroll
    for (int e = d; e < DD * HH; e += 128) ((float*)w1_s)[e] = gw1[e];
    __syncthreads();

    #pragma unroll 4
    for (int n = 0; n < NN; n++) {
        size_t base = (size_t)idx_s[n] * 128 + d;
        float k0 = k0p[base], k1 = k1p[base], k2 = k2p[base];
        float dot = q0 * k0 + q1 * k1 + q2 * k2;
        dot += __shfl_xor_sync(0xffffffffu, dot, 8);
        dot += __shfl_xor_sync(0xffffffffu, dot, 4);
        dot += __shfl_xor_sync(0xffffffffu, dot, 2);
        dot += __shfl_xor_sync(0xffffffffu, dot, 1);
        if ((d & 15) == 0) att_s[n][h] = dot;
        pos_s[n][d] = (k0 - q0) * sh_s[n][0] + (k1 - q1) * sh_s[n][1]
                    + (k2 - q2) * sh_s[n][2];
    }
    __syncthreads();

    {
        int n = d >> 3, j = d & 7;
        float acc = gb1[j];
        const float4* pv = reinterpret_cast<const float4*>(&pos_s[n][0]);
        #pragma unroll 8
        for (int c4 = 0; c4 < DD / 4; c4++) {
            float4 pp = pv[c4];
            acc += pp.x * w1_s[c4 * 4 + 0][j] + pp.y * w1_s[c4 * 4 + 1][j]
                 + pp.z * w1_s[c4 * 4 + 2][j] + pp.w * w1_s[c4 * 4 + 3][j];
        }
        rh_s[n][j] = fmaxf(acc, 0.0f);
    }
    __syncthreads();

    {
        int n = d >> 3, hh = d & 7;
        float acc = gb2[hh];
        #pragma unroll
        for (int j = 0; j < HH; j++) acc += rh_s[n][j] * gw2[j * HH + hh];
        float da = dist[(size_t)p * (NN * HH) + n * HH + hh];
        att_s[n][hh] = (att_s[n][hh] + acc + da) * 0.25f;
    }
    __syncthreads();

    if (d < HH) {
        float m = -1e30f;
        #pragma unroll
        for (int n = 0; n < NN; n++) m = fmaxf(m, att_s[n][d]);
        float s = 0.f;
        #pragma unroll
        for (int n = 0; n < NN; n++) { float e = expf(att_s[n][d] - m); att_s[n][d] = e; s += e; }
        float inv = 1.f / s;
        #pragma unroll
        for (int n = 0; n < NN; n++) att_s[n][d] *= inv;
    }
    __syncthreads();

    float o0 = 0.f, o1 = 0.f, o2 = 0.f;
    #pragma unroll 4
    for (int n = 0; n < NN; n++) {
        float a = att_s[n][h];
        size_t base = (size_t)idx_s[n] * 128 + d;
        o0 += a * v0p[base];
        o1 += a * v1p[base];
        o2 += a * v2p[base];
    }
    float* op = g_t2 + (size_t)p * (DD * 3) + d * 3;
    op[0] = o0; op[1] = o1; op[2] = o2;
}

// ---------------------------------------------------------------------------
// Fused residual + vn_layernorm: O = vn_ln(A + B).
// A interleaved, B plane-major (fully coalesced reads), O interleaved.
// ---------------------------------------------------------------------------
__global__ void vn_ln_plB_kernel(const float* __restrict__ A,
                                 const float* __restrict__ B,
                                 const float* __restrict__ gam,
                                 const float* __restrict__ bet,
                                 float* __restrict__ O)
{
    const int p = blockIdx.x;
    const int d = threadIdx.x;
    size_t base = (size_t)p * (DD * 3) + d * 3;
    size_t pbse = (size_t)p * 128 + d;
    float z0 = A[base + 0] + B[pbse];
    float z1 = A[base + 1] + B[PL + pbse];
    float z2 = A[base + 2] + B[2 * PL + pbse];
    float n = sqrtf(z0 * z0 + z1 * z1 + z2 * z2);

    float s1 = n, s2 = n * n;
    #pragma unroll
    for (int off = 16; off; off >>= 1) {
        s1 += __shfl_xor_sync(0xffffffffu, s1, off);
        s2 += __shfl_xor_sync(0xffffffffu, s2, off);
    }
    __shared__ float sm1[4], sm2[4];
    int w = d >> 5;
    if ((d & 31) == 0) { sm1[w] = s1; sm2[w] = s2; }
    __syncthreads();
    float S1 = sm1[0] + sm1[1] + sm1[2] + sm1[3];
    float S2 = sm2[0] + sm2[1] + sm2[2] + sm2[3];
    float mu  = S1 * (1.0f / DD);
    float var = S2 * (1.0f / DD) - mu * mu;
    float nh  = (n - mu) * rsqrtf(var + 1e-5f) * gam[d] + bet[d];
    float sc  = nh / (n + 1e-6f);
    O[base + 0] = z0 * sc;
    O[base + 1] = z1 * sc;
    O[base + 2] = z2 * sc;
}

// ---------------------------------------------------------------------------
extern "C" void kernel_launch(void* const* d_in, const int* in_sizes, int n_in,
                              void* d_out, int out_size)
{
    const float* tgt   = (const float*)d_in[0];
    const float* mem   = (const float*)d_in[1];
    const float* sh    = (const float*)d_in[2];
    const float* dist  = (const float*)d_in[3];
    const float* Wq    = (const float*)d_in[4];
    const float* Wk    = (const float*)d_in[5];
    const float* Wv    = (const float*)d_in[6];
    const float* Wo    = (const float*)d_in[7];
    const float* gw1   = (const float*)d_in[8];
    const float* gb1   = (const float*)d_in[9];
    const float* gw2   = (const float*)d_in[10];
    const float* gb2   = (const float*)d_in[11];
    const float* ln1g  = (const float*)d_in[12];
    const float* ln1b  = (const float*)d_in[13];
    const float* ln2g  = (const float*)d_in[14];
    const float* ln2b  = (const float*)d_in[15];
    const float* ffw1  = (const float*)d_in[16];
    const float* ffd1  = (const float*)d_in[17];
    const float* ffw2  = (const float*)d_in[18];
    const int*   idxp  = (const int*)d_in[19];
    float* out = (float*)d_out;

    float *q, *k, *v, *t2, *t2o, *y, *h1, *ff;
    cudaGetSymbolAddress((void**)&q,   g_q);
    cudaGetSymbolAddress((void**)&k,   g_k);
    cudaGetSymbolAddress((void**)&v,   g_v);
    cudaGetSymbolAddress((void**)&t2,  g_t2);
    cudaGetSymbolAddress((void**)&t2o, g_t2o);
    cudaGetSymbolAddress((void**)&y,   g_y);
    cudaGetSymbolAddress((void**)&h1,  g_h1);
    cudaGetSymbolAddress((void**)&ff,  g_ff);
    float2 *wdD, *wd2;
    cudaGetSymbolAddress((void**)&wdD, g_WdD);
    cudaGetSymbolAddress((void**)&wd2, g_Wd2);

    const int NT = PP / 32;   // 625 point tiles

    dup_weights<<<1024, 256>>>(Wq, Wk, Wv, Wo, ffw1, ffd1, ffw2);

    // merged q/k/v: 1875 CTAs, which = bid % 3
    qkv_gemm<<<NT * 3, 128>>>(tgt, mem, q, k, v);

    attn_kernel<<<PP, 128>>>(sh, dist, gw1, gb1, gw2, gb2, idxp);

    vn_gemm_db_pl<DD><<<NT, 128>>>(t2, wdD + 3 * 16384, t2o);      // plane t2o
    vn_ln_plB_kernel<<<PP, 128>>>(tgt, t2o, ln1g, ln1b, y);

    vn_ff1_db<<<dim3(DFF / 64, NT), 128>>>(y, h1);
    vn_gemm_cs_db_pl<DFF><<<NT * 2, 128>>>(h1, wd2, ff);           // plane ff
    vn_ln_plB_kernel<<<PP, 128>>>(y, ff, ln2g, ln2b, out);
}